// round 17
// baseline (speedup 1.0000x reference)
#include <cuda_runtime.h>
#include <cuda_bf16.h>

#define N_PROP 128
#define N_GRIDP 216
#define G_TOT  27648
#define N_KEY  4096
#define C_FEAT 128
#define NS     16
#define K_RED  27648
#define KSPLIT 72
#define KCHUNK 384
#define NCHUNK 3456              // 2 * 27648 / 16
#define GR     30                // hash cells per axis
#define NCELL  27000             // 30^3
#define CELL_INV 0.625f          // 1/1.6
#define CELL_OFF 24.0f

typedef unsigned long long ull;

// ---------------- scratch ----------------
static __device__ float  d_grid[G_TOT * 3];
static __device__ float2 d_A[2][N_KEY * 32];    // A' = g1*A + b1, packed (c, c+32)
static __device__ int    d_idx[2][G_TOT * NS];
static __device__ int    d_cnt[2][G_TOT];
static __device__ float  d_perm[N_PROP * K_RED];
static __device__ float  d_partial[KSPLIT][N_PROP * 256];
static __device__ float  d_hbuf[N_PROP * 256];
static __device__ float  d_w2t[256 * 256];
static __device__ unsigned d_work;
// hash grid
static __device__ int    d_cellcnt[NCELL];
static __device__ int    d_cellfill[NCELL];
static __device__ int    d_cellstart[NCELL + 1];
static __device__ float4 d_ksorted[N_KEY];
static __device__ int    d_kidx[N_KEY];

// ---------------- f32x2 helpers ----------------
__device__ __forceinline__ ull splat2(float x) {
    ull r;
    asm("mov.b64 %0, {%1, %1};" : "=l"(r) : "f"(x));
    return r;
}
__device__ __forceinline__ void fma2(ull& acc, ull a, ull b) {
    asm("fma.rn.f32x2 %0, %1, %2, %0;" : "+l"(acc) : "l"(a), "l"(b));
}
__device__ __forceinline__ float2 unpack2(ull v) {
    float lo, hi;
    asm("mov.b64 {%0, %1}, %2;" : "=f"(lo), "=f"(hi) : "l"(v));
    return make_float2(lo, hi);
}
__device__ __forceinline__ ull d2u(double d) { return __double_as_longlong(d); }

__device__ __forceinline__ int cellco(float x) {
    int c = (int)floorf((x + CELL_OFF) * CELL_INV);
    return min(max(c, 0), GR - 1);
}

// ---------------- k1: grid points (+ counters reset) ----------------
__global__ void k_grid(const float* __restrict__ wlh, const float* __restrict__ center,
                       const float* __restrict__ yaw, const float* __restrict__ u)
{
    int g = blockIdx.x * 256 + threadIdx.x;
    if (g == 0) d_work = 0u;
    if (g < NCELL) { d_cellcnt[g] = 0; d_cellfill[g] = 0; }
    if (g >= G_TOT) return;
    int ni = g / N_GRIDP;
    float gx = u[g * 3 + 0] * wlh[ni * 3 + 0];
    float gy = u[g * 3 + 1] * wlh[ni * 3 + 1];
    float gz = u[g * 3 + 2] * wlh[ni * 3 + 2];
    float yv = yaw[ni];
    float c = cosf(yv), s = sinf(yv);
    float rx = c * gx - s * gy;
    float ry = s * gx + c * gy;
    d_grid[g * 3 + 0] = rx + center[ni * 3 + 0];
    d_grid[g * 3 + 1] = ry + center[ni * 3 + 1];
    d_grid[g * 3 + 2] = gz + center[ni * 3 + 2];
}

// ---------------- hash grid build ----------------
__global__ void k_bincount(const float* __restrict__ kp)
{
    int k = blockIdx.x * 256 + threadIdx.x;
    if (k >= N_KEY) return;
    int cx = cellco(kp[k * 3 + 0]), cy = cellco(kp[k * 3 + 1]), cz = cellco(kp[k * 3 + 2]);
    atomicAdd(&d_cellcnt[(cz * GR + cy) * GR + cx], 1);
}

__global__ void __launch_bounds__(1024) k_scan()
{
    __shared__ int s[1024];
    __shared__ int carry;
    int tid = threadIdx.x;
    if (tid == 0) carry = 0;
    __syncthreads();
    for (int chunk = 0; chunk < (NCELL + 1023) / 1024; chunk++) {
        int i = chunk * 1024 + tid;
        int v = (i < NCELL) ? d_cellcnt[i] : 0;
        s[tid] = v;
        __syncthreads();
#pragma unroll
        for (int off = 1; off < 1024; off <<= 1) {
            int t = (tid >= off) ? s[tid - off] : 0;
            __syncthreads();
            s[tid] += t;
            __syncthreads();
        }
        if (i < NCELL) d_cellstart[i] = carry + s[tid] - v;
        __syncthreads();
        if (tid == 1023) carry += s[1023];
        __syncthreads();
    }
    if (tid == 0) d_cellstart[NCELL] = N_KEY;
}

__global__ void k_scatter(const float* __restrict__ kp)
{
    int k = blockIdx.x * 256 + threadIdx.x;
    if (k >= N_KEY) return;
    float kx = kp[k * 3 + 0], ky = kp[k * 3 + 1], kz = kp[k * 3 + 2];
    int cx = cellco(kx), cy = cellco(ky), cz = cellco(kz);
    int cell = (cz * GR + cy) * GR + cx;
    int pos = d_cellstart[cell] + atomicAdd(&d_cellfill[cell], 1);
    d_ksorted[pos] = make_float4(kx, ky, kz, kx * kx + ky * ky + kz * kz);
    d_kidx[pos] = k;
}

// ---------------- k3: hash-grid ball query, thread per gridpoint ----------------
// Maintains sorted list of <=16 smallest hit indices per radius == reference's
// sort(candidates)[:16]. Pads with first (smallest) hit; cnt = max(n,1).
__device__ __forceinline__ void ins16(int* l, int& n, int ki)
{
    if (n < NS) {
        int p = n++;
        while (p > 0 && l[p - 1] > ki) { l[p] = l[p - 1]; p--; }
        l[p] = ki;
    } else if (ki < l[NS - 1]) {
        int p = NS - 1;
        while (p > 0 && l[p - 1] > ki) { l[p] = l[p - 1]; p--; }
        l[p] = ki;
    }
}

__global__ void __launch_bounds__(256) k_ball(const float* __restrict__ unused)
{
    extern __shared__ __align__(16) char bsm[];
    float4* ks = (float4*)bsm;                  // 64 KB
    int* ki = (int*)(bsm + N_KEY * 16);         // 16 KB
    int* cstart = (int*)(bsm + N_KEY * 20);     // (NCELL+1) ints = 105.5 KB more? too big
    // NOTE: cell starts stay in gmem/L2 (27001 ints); only key data staged in smem.
    int tid = threadIdx.x;
    for (int k = tid; k < N_KEY; k += 256) {
        ks[k] = d_ksorted[k];
        ki[k] = d_kidx[k];
    }
    __syncthreads();
    (void)cstart;

    int g = blockIdx.x * 256 + tid;
    float gx = d_grid[g * 3 + 0], gy = d_grid[g * 3 + 1], gz = d_grid[g * 3 + 2];
    float gs = gx * gx + gy * gy + gz * gz;
    float m2x = -2.f * gx, m2y = -2.f * gy, m2z = -2.f * gz;

    int cx = cellco(gx), cy = cellco(gy), cz = cellco(gz);
    int x0 = max(cx - 1, 0), x1 = min(cx + 1, GR - 1);
    int y0 = max(cy - 1, 0), y1 = min(cy + 1, GR - 1);
    int z0 = max(cz - 1, 0), z1 = min(cz + 1, GR - 1);

    int l0[NS], l1[NS];
    int n0 = 0, n1 = 0;

#pragma unroll 1
    for (int zz = z0; zz <= z1; zz++) {
#pragma unroll 1
        for (int yy = y0; yy <= y1; yy++) {
            int rowbase = (zz * GR + yy) * GR;
            int cs = d_cellstart[rowbase + x0];
            int ce = d_cellstart[rowbase + x1 + 1];
#pragma unroll 1
            for (int j = cs; j < ce; j++) {
                float4 v = ks[j];
                float d2 = fmaf(m2x, v.x, fmaf(m2y, v.y, fmaf(m2z, v.z, gs + v.w)));
                if (d2 < 2.56f) {
                    int kk = ki[j];
                    ins16(l1, n1, kk);
                    if (d2 < 0.64f) ins16(l0, n0, kk);
                }
            }
        }
    }

    int f1 = (n1 > 0) ? l1[0] : 0;
    int f0 = (n0 > 0) ? l0[0] : 0;
    int* o0 = &d_idx[0][g * NS];
    int* o1 = &d_idx[1][g * NS];
#pragma unroll
    for (int n = 0; n < NS; n++) {
        o1[n] = (n < n1) ? l1[n] : f1;
        o0[n] = (n < n0) ? l0[n] : f0;
    }
    d_cnt[0][g] = (n0 > 0) ? n0 : 1;
    d_cnt[1][g] = (n1 > 0) ? n1 : 1;
}

// ---------------- k2: per-keypoint A' = g1*(kp.w1[:3] + kf.w1[3:]) + b1 -------
__global__ void __launch_bounds__(256) k_A(const float* __restrict__ kp, const float* __restrict__ kf,
                                           const float* __restrict__ w1_0, const float* __restrict__ w1_1,
                                           const float* __restrict__ g1_0, const float* __restrict__ g1_1,
                                           const float* __restrict__ b1_0, const float* __restrict__ b1_1)
{
    __shared__ float w1s[64 * 131];
    extern __shared__ float kfs[];            // 128 c x 64 k = 32 KB dynamic
    const float* w1 = blockIdx.y ? w1_1 : w1_0;
    const float* g1 = blockIdx.y ? g1_1 : g1_0;
    const float* b1 = blockIdx.y ? b1_1 : b1_0;
    int tid = threadIdx.y * 32 + threadIdx.x;
    for (int i = tid; i < 64 * 131; i += 256) w1s[i] = w1[i];

    int kbase = blockIdx.x * 64;
    for (int e = tid; e < C_FEAT * 64; e += 256) {
        int c = e >> 6, kk = e & 63;
        kfs[c * 64 + kk] = kf[c * N_KEY + kbase + kk];
    }
    __syncthreads();

    int l = threadIdx.x;
    float g1lo = g1[l], g1hi = g1[l + 32];
    float b1lo = b1[l], b1hi = b1[l + 32];
#pragma unroll 1
    for (int t = 0; t < 8; t++) {
        int kk = t * 8 + threadIdx.y;
        int k = kbase + kk;
        float kx = kp[k * 3 + 0], ky = kp[k * 3 + 1], kz = kp[k * 3 + 2];
        float a0 = w1s[l * 131 + 0] * kx + w1s[l * 131 + 1] * ky + w1s[l * 131 + 2] * kz;
        float a1 = w1s[(l + 32) * 131 + 0] * kx + w1s[(l + 32) * 131 + 1] * ky + w1s[(l + 32) * 131 + 2] * kz;
#pragma unroll 4
        for (int c = 0; c < C_FEAT; c++) {
            float f = kfs[c * 64 + kk];
            a0 = fmaf(f, w1s[l * 131 + 3 + c], a0);
            a1 = fmaf(f, w1s[(l + 32) * 131 + 3 + c], a1);
        }
        d_A[blockIdx.y][k * 32 + l] = make_float2(fmaf(g1lo, a0, b1lo), fmaf(g1hi, a1, b1hi));
    }
}

// ---------------- k4: branch MLP + maxpool, adaptive 4/8-sample groups -------
__device__ __forceinline__ void kb_group(
    const float2* p, int nsmp, float* hb,
    const float (*w2b)[64][4], int lane,
    float qlo, float qhi, float g2lo, float g2hi, float b2lo, float b2hi,
    float& mxA, float& mxB)
{
#pragma unroll
    for (int s = 0; s < 8; s++) {
        if (s < nsmp) {
            hb[s * 64 + lane]      = fmaxf(p[s].x - qlo, 0.f);
            hb[s * 64 + lane + 32] = fmaxf(p[s].y - qhi, 0.f);
        }
    }
    __syncwarp();

    ull accLo[8], accHi[8];
#pragma unroll
    for (int s = 0; s < 8; s++) { accLo[s] = 0; accHi[s] = 0; }

#pragma unroll
    for (int jj = 0; jj < 8; jj++) {
        double2 dAlo = *(const double2*)&w2b[2 * jj][lane][0];
        double2 dBlo = *(const double2*)&w2b[2 * jj + 1][lane][0];
        double2 dAhi = *(const double2*)&w2b[2 * jj][lane + 32][0];
        double2 dBhi = *(const double2*)&w2b[2 * jj + 1][lane + 32][0];
        ull wl0 = d2u(dAlo.x), wl1 = d2u(dAlo.y);
        ull wl2 = d2u(dBlo.x), wl3 = d2u(dBlo.y);
        ull wh0 = d2u(dAhi.x), wh1 = d2u(dAhi.y);
        ull wh2 = d2u(dBhi.x), wh3 = d2u(dBhi.y);
#pragma unroll
        for (int s = 0; s < 8; s++) {
            if (s < nsmp) {
                const double2* hs = (const double2*)(hb + s * 64);
                double2 v0 = hs[2 * jj], v1 = hs[2 * jj + 1];
                fma2(accLo[s], d2u(v0.x), wl0); fma2(accLo[s], d2u(v0.y), wl1);
                fma2(accLo[s], d2u(v1.x), wl2); fma2(accLo[s], d2u(v1.y), wl3);
                fma2(accHi[s], d2u(v0.x), wh0); fma2(accHi[s], d2u(v0.y), wh1);
                fma2(accHi[s], d2u(v1.x), wh2); fma2(accHi[s], d2u(v1.y), wh3);
            }
        }
    }
    __syncwarp();

#pragma unroll
    for (int s = 0; s < 8; s++) {
        if (s < nsmp) {
            float2 pl = unpack2(accLo[s]);
            float2 ph = unpack2(accHi[s]);
            mxA = fmaxf(mxA, fmaf(g2lo, pl.x + pl.y, b2lo));
            mxB = fmaxf(mxB, fmaf(g2hi, ph.x + ph.y, b2hi));
        }
    }
}

__global__ void __launch_bounds__(256, 2) k_branch(
    const float* __restrict__ w1_0, const float* __restrict__ g1_0,
    const float* __restrict__ w2_0, const float* __restrict__ g2_0, const float* __restrict__ b2_0,
    const float* __restrict__ w1_1, const float* __restrict__ g1_1,
    const float* __restrict__ w2_1, const float* __restrict__ g2_1, const float* __restrict__ b2_1)
{
    const int lane = threadIdx.x & 31;
    const int warp = threadIdx.x >> 5;
    const int tid  = threadIdx.x;

    __shared__ __align__(16) float w2s[2][16][64][4];   // 32 KB static
    extern __shared__ __align__(16) float dynbuf[];     // 8 warps x 8 smp x 64 = 16 KB
    __shared__ int s_chunk;
    float* hb = dynbuf + warp * 8 * 64;

    for (int e = tid; e < 2 * 64 * 64; e += 256) {
        int b = e >> 12, r = e & 4095, o = r >> 6, c = r & 63;
        const float* w2 = b ? w2_1 : w2_0;
        w2s[b][c >> 2][o][c & 3] = w2[o * 64 + c];
    }

    int cur_b = -1;
    float g2lo = 0, g2hi = 0, b2lo = 0, b2hi = 0;
    float g1lo = 0, g1hi = 0;
    float w1x0 = 0, w1y0 = 0, w1z0 = 0, w1x1 = 0, w1y1 = 0, w1z1 = 0;
    const float2* A2 = d_A[0];
    const int*    idxp = d_idx[0];
    const int*    cntp = d_cnt[0];

    for (;;) {
        __syncthreads();
        if (tid == 0) s_chunk = (int)atomicAdd(&d_work, 1u);
        __syncthreads();
        int chunk = s_chunk;
        if (chunk >= NCHUNK) break;

        int b = (chunk >= NCHUNK / 2);
        int gbase = (chunk - b * (NCHUNK / 2)) * 16;

        if (b != cur_b) {
            cur_b = b;
            const float* w1 = b ? w1_1 : w1_0;
            const float* g1 = b ? g1_1 : g1_0;
            const float* g2 = b ? g2_1 : g2_0;
            const float* b2 = b ? b2_1 : b2_0;
            g2lo = g2[lane]; g2hi = g2[lane + 32];
            b2lo = b2[lane]; b2hi = b2[lane + 32];
            g1lo = g1[lane]; g1hi = g1[lane + 32];
            w1x0 = w1[lane * 131 + 0]; w1y0 = w1[lane * 131 + 1]; w1z0 = w1[lane * 131 + 2];
            w1x1 = w1[(lane + 32) * 131 + 0]; w1y1 = w1[(lane + 32) * 131 + 1]; w1z1 = w1[(lane + 32) * 131 + 2];
            A2 = d_A[b];
            idxp = d_idx[b];
            cntp = d_cnt[b];
        }

        const float (*w2b)[64][4] = w2s[b];

#pragma unroll 1
        for (int gi = 0; gi < 2; gi++) {
            int g = gbase + warp * 2 + gi;
            float gx = d_grid[g * 3 + 0], gy = d_grid[g * 3 + 1], gz = d_grid[g * 3 + 2];
            float qlo = g1lo * (w1x0 * gx + w1y0 * gy + w1z0 * gz);
            float qhi = g1hi * (w1x1 * gx + w1y1 * gy + w1z1 * gz);
            int cnt = cntp[g];
            int cm1 = cnt - 1;
            int kreg = idxp[g * NS + (lane & 15)];
            float mxA = -1e30f, mxB = -1e30f;

            float2 p[8];
            if (cnt <= 4) {
#pragma unroll
                for (int s = 0; s < 4; s++) {
                    int idx = (s < cm1) ? s : cm1;
                    p[s] = A2[__shfl_sync(0xffffffffu, kreg, idx) * 32 + lane];
                }
                kb_group(p, 4, hb, w2b, lane, qlo, qhi, g2lo, g2hi, b2lo, b2hi, mxA, mxB);
            } else {
#pragma unroll
                for (int s = 0; s < 8; s++) {
                    int idx = (s < cm1) ? s : cm1;
                    p[s] = A2[__shfl_sync(0xffffffffu, kreg, idx) * 32 + lane];
                }
                kb_group(p, 8, hb, w2b, lane, qlo, qhi, g2lo, g2hi, b2lo, b2hi, mxA, mxB);
                if (cnt > 8) {
#pragma unroll
                    for (int s = 0; s < 8; s++) {
                        int idx = (8 + s < cm1) ? 8 + s : cm1;
                        p[s] = A2[__shfl_sync(0xffffffffu, kreg, idx) * 32 + lane];
                    }
                    kb_group(p, 8, hb, w2b, lane, qlo, qhi, g2lo, g2hi, b2lo, b2hi, mxA, mxB);
                }
            }

            int ni = g / N_GRIDP, mi = g % N_GRIDP;
            int cpA = b * 64 + lane;
            d_perm[mi * 16384 + cpA * 128 + ni] = fmaxf(mxA, 0.f);
            d_perm[mi * 16384 + (cpA + 32) * 128 + ni] = fmaxf(mxB, 0.f);
        }
    }
}

// ---------------- k5: reduction GEMM layer1, split-K=72, f32x2 ----------------
__global__ void __launch_bounds__(256) k_red1(const float* __restrict__ W)
{
    __shared__ __align__(16) float As[32][132];
    __shared__ __align__(16) float Bs[32][68];
    const int ob = blockIdx.x * 64;
    const int kbase = blockIdx.y * KCHUNK;
    const int tid = threadIdx.x;
    const int tx = tid & 15, ty = tid >> 4;

    ull acc[4][4];
#pragma unroll
    for (int r = 0; r < 4; r++)
#pragma unroll
        for (int c = 0; c < 4; c++) acc[r][c] = 0;

    for (int kc = 0; kc < KCHUNK; kc += 32) {
        int k0 = kbase + kc;
#pragma unroll
        for (int r = 0; r < 16; r++) {
            int e = tid + 256 * r;
            int i = e >> 5, kk = e & 31;
            As[kk][i] = d_perm[i * K_RED + k0 + kk];
        }
#pragma unroll
        for (int r = 0; r < 8; r++) {
            int e = tid + 256 * r;
            int o = e >> 5, kk = e & 31;
            Bs[kk][o] = W[(ob + o) * K_RED + k0 + kk];
        }
        __syncthreads();
#pragma unroll
        for (int kk = 0; kk < 32; kk++) {
            double2 a01 = *(const double2*)&As[kk][ty * 8];
            double2 a23 = *(const double2*)&As[kk][ty * 8 + 4];
            float4 bv = *(const float4*)&Bs[kk][tx * 4];
            ull ap0 = d2u(a01.x), ap1 = d2u(a01.y), ap2 = d2u(a23.x), ap3 = d2u(a23.y);
            ull b0 = splat2(bv.x), b1 = splat2(bv.y), b2 = splat2(bv.z), b3 = splat2(bv.w);
            fma2(acc[0][0], ap0, b0); fma2(acc[0][1], ap0, b1); fma2(acc[0][2], ap0, b2); fma2(acc[0][3], ap0, b3);
            fma2(acc[1][0], ap1, b0); fma2(acc[1][1], ap1, b1); fma2(acc[1][2], ap1, b2); fma2(acc[1][3], ap1, b3);
            fma2(acc[2][0], ap2, b0); fma2(acc[2][1], ap2, b1); fma2(acc[2][2], ap2, b2); fma2(acc[2][3], ap2, b3);
            fma2(acc[3][0], ap3, b0); fma2(acc[3][1], ap3, b1); fma2(acc[3][2], ap3, b2); fma2(acc[3][3], ap3, b3);
        }
        __syncthreads();
    }
    float* outp = d_partial[blockIdx.y];
#pragma unroll
    for (int rp = 0; rp < 4; rp++)
#pragma unroll
        for (int c = 0; c < 4; c++) {
            float2 v = unpack2(acc[rp][c]);
            outp[(ty * 8 + 2 * rp) * 256 + ob + tx * 4 + c] = v.x;
            outp[(ty * 8 + 2 * rp + 1) * 256 + ob + tx * 4 + c] = v.y;
        }
}

// ---------------- k6: partial reduce + bias + relu ----------------
__global__ void k_redfin(const float* __restrict__ b1)
{
    int t = blockIdx.x * 256 + threadIdx.x;
    float s = b1[t & 255];
#pragma unroll
    for (int ks = 0; ks < KSPLIT; ks++) s += d_partial[ks][t];
    d_hbuf[t] = fmaxf(s, 0.f);
}

// ---------------- k6b: transpose W2 ----------------
__global__ void k_w2t(const float* __restrict__ W2)
{
    __shared__ float tbuf[32][33];
    int x = blockIdx.x * 32 + threadIdx.x;
    int y0 = blockIdx.y * 32;
#pragma unroll
    for (int r = threadIdx.y; r < 32; r += 8)
        tbuf[r][threadIdx.x] = W2[(y0 + r) * 256 + x];
    __syncthreads();
    int xo = blockIdx.y * 32 + threadIdx.x;
#pragma unroll
    for (int r = threadIdx.y; r < 32; r += 8)
        d_w2t[(blockIdx.x * 32 + r) * 256 + xo] = tbuf[threadIdx.x][r];
}

// ---------------- k7: layer2 256x256 + relu ----------------
__global__ void __launch_bounds__(256) k_red2(const float* __restrict__ b2, float* __restrict__ out)
{
    __shared__ float hs[256];
    int i = blockIdx.x;
    hs[threadIdx.x] = d_hbuf[i * 256 + threadIdx.x];
    __syncthreads();
    int o = threadIdx.x;
    float s = b2[o];
#pragma unroll 8
    for (int c = 0; c < 256; c++) s = fmaf(hs[c], d_w2t[c * 256 + o], s);
    out[i * 256 + o] = fmaxf(s, 0.f);
}

// ---------------- launch ----------------
extern "C" void kernel_launch(void* const* d_in, const int* in_sizes, int n_in,
                              void* d_out, int out_size)
{
    const float* wlh    = (const float*)d_in[0];
    const float* center = (const float*)d_in[1];
    const float* yaw    = (const float*)d_in[2];
    const float* u      = (const float*)d_in[3];
    const float* kp     = (const float*)d_in[4];
    const float* kf     = (const float*)d_in[5];
    const float* pn0_w1 = (const float*)d_in[6];
    const float* pn0_g1 = (const float*)d_in[7];
    const float* pn0_b1 = (const float*)d_in[8];
    const float* pn0_w2 = (const float*)d_in[9];
    const float* pn0_g2 = (const float*)d_in[10];
    const float* pn0_b2 = (const float*)d_in[11];
    const float* pn1_w1 = (const float*)d_in[12];
    const float* pn1_g1 = (const float*)d_in[13];
    const float* pn1_b1 = (const float*)d_in[14];
    const float* pn1_w2 = (const float*)d_in[15];
    const float* pn1_g2 = (const float*)d_in[16];
    const float* pn1_b2 = (const float*)d_in[17];
    const float* red_w1 = (const float*)d_in[18];
    const float* red_b1 = (const float*)d_in[19];
    const float* red_w2 = (const float*)d_in[20];
    const float* red_b2 = (const float*)d_in[21];
    float* out = (float*)d_out;

    cudaFuncSetAttribute(k_ball,   cudaFuncAttributeMaxDynamicSharedMemorySize, N_KEY * 20);
    cudaFuncSetAttribute(k_A,      cudaFuncAttributeMaxDynamicSharedMemorySize, 32768);
    cudaFuncSetAttribute(k_branch, cudaFuncAttributeMaxDynamicSharedMemorySize, 16384);

    k_grid<<<(G_TOT + 255) / 256, 256>>>(wlh, center, yaw, u);
    k_bincount<<<(N_KEY + 255) / 256, 256>>>(kp);
    k_scan<<<1, 1024>>>();
    k_scatter<<<(N_KEY + 255) / 256, 256>>>(kp);
    k_ball<<<G_TOT / 256, 256, N_KEY * 20>>>(kp);
    k_A<<<dim3(64, 2), dim3(32, 8), 32768>>>(kp, kf, pn0_w1, pn1_w1,
                                             pn0_g1, pn1_g1, pn0_b1, pn1_b1);
    k_branch<<<296, 256, 16384>>>(pn0_w1, pn0_g1, pn0_w2, pn0_g2, pn0_b2,
                                  pn1_w1, pn1_g1, pn1_w2, pn1_g2, pn1_b2);
    k_w2t<<<dim3(8, 8), dim3(32, 8)>>>(red_w2);
    k_red1<<<dim3(4, KSPLIT), 256>>>(red_w1);
    k_redfin<<<128, 256>>>(red_b1);
    k_red2<<<128, 256>>>(red_b2, out);
}